// round 5
// baseline (speedup 1.0000x reference)
#include <cuda_runtime.h>

#define N_COLS 65536
#define BATCH   256
#define THREADS 256
#define QB      64                     // x-quads per block (= 128 columns)
#define ROW_STRIDE (N_COLS / 2)        // row stride in float4 (x) / float2 (out) units
#define RGROUPS 4                      // row-groups (threads 256 / QB)
#define ITERS   (BATCH / RGROUPS)      // 64 rows per thread
#define LBATCH  8                      // loads batched per inner block

// W16_TO_4 exactly as the reference builds it (W[3,1] written twice -> final 1).
__constant__ float c_W[4][16] = {
    { 0, 0, 0, 0,  0, 0, 0, 0,   1,  1,  1,  1,   1,  1,  1,  1},
    { 0, 0, 1, 1,  0, 0, 1, 1,  -1, -1,  0,  0,  -1, -1,  0,  0},
    { 0, 0, 0, 0,  1, 1, 1, 1,  -1, -1, -1, -1,   0,  0,  0,  0},
    { 0, 1,-1, 0, -1, 0,-2,-1,   1,  2,  0,  1,   0,  1, -1,  0}
};

// Fused kernel: each block owns 128 columns (64 x-quads) x ALL 256 rows.
// Prologue: threads 0..127 compute softmax+projection for one column each
// (each column's exp computed exactly ONCE chip-wide), coeffs -> smem.
// Main loop: 64 rows/thread, unit-stride LDG.128 across the warp, coeffs in
// registers, 8-deep load batches for MLP. MUFU work hides under DRAM time.
__global__ void __launch_bounds__(THREADS, 4)
fused_gate_kernel(const float4* __restrict__ x, const float* __restrict__ w,
                  float2* __restrict__ out) {
    __shared__ float4 s_wc[2 * QB];    // {c0,c1,c2,c3} per column, 2KB

    const int tid = threadIdx.x;
    const int blk = blockIdx.x;

    // ---- Prologue: per-column softmax -> 4 coefficients ----
    if (tid < 2 * QB) {
        const int col = blk * (2 * QB) + tid;
        float v[16];
        float m = -1e30f;
#pragma unroll
        for (int k = 0; k < 16; k++) {
            v[k] = __ldg(&w[k * N_COLS + col]);
            m = fmaxf(m, v[k]);
        }
        float s = 0.0f;
#pragma unroll
        for (int k = 0; k < 16; k++) {
            v[k] = __expf(v[k] - m);
            s += v[k];
        }
        float inv = 1.0f / s;

        float c0 = 0.f, c1 = 0.f, c2 = 0.f, c3 = 0.f;
#pragma unroll
        for (int k = 0; k < 16; k++) {
            c0 = fmaf(c_W[0][k], v[k], c0);
            c1 = fmaf(c_W[1][k], v[k], c1);
            c2 = fmaf(c_W[2][k], v[k], c2);
            c3 = fmaf(c_W[3][k], v[k], c3);
        }
        s_wc[tid] = make_float4(c0 * inv, c1 * inv, c2 * inv, c3 * inv);
    }
    __syncthreads();

    // ---- Main streaming loop ----
    const int tq = tid & (QB - 1);     // quad within block [0,64)
    const int tr = tid >> 6;           // row-group [0,4)
    const int gq = blk * QB + tq;      // global x-quad -> columns 2gq, 2gq+1

    const float4 w0 = s_wc[2 * tq];
    const float4 w1 = s_wc[2 * tq + 1];

    const float4* xp = x   + (size_t)tr * ROW_STRIDE + gq;
    float2*       op = out + (size_t)tr * ROW_STRIDE + gq;

#pragma unroll
    for (int h = 0; h < ITERS / LBATCH; h++) {
        float4 a[LBATCH];
#pragma unroll
        for (int i = 0; i < LBATCH; i++)
            a[i] = __ldg(xp + (size_t)(RGROUPS * i) * ROW_STRIDE);
#pragma unroll
        for (int i = 0; i < LBATCH; i++) {
            float2 r;
            // out = c0 + c1*A + c2*B + c3*A*B = fma(A, fma(B,c3,c1), fma(B,c2,c0))
            r.x = fmaf(a[i].x, fmaf(a[i].y, w0.w, w0.y), fmaf(a[i].y, w0.z, w0.x));
            r.y = fmaf(a[i].z, fmaf(a[i].w, w1.w, w1.y), fmaf(a[i].w, w1.z, w1.x));
            op[(size_t)(RGROUPS * i) * ROW_STRIDE] = r;
        }
        xp += (size_t)(RGROUPS * LBATCH) * ROW_STRIDE;
        op += (size_t)(RGROUPS * LBATCH) * ROW_STRIDE;
    }
}

extern "C" void kernel_launch(void* const* d_in, const int* in_sizes, int n_in,
                              void* d_out, int out_size) {
    const float* x = (const float*)d_in[0];   // (256, 131072)
    const float* w = (const float*)d_in[1];   // (16, 65536)
    float* out = (float*)d_out;               // (256, 65536)

    // 512 blocks x 128 columns = 65536 columns; one wave at 4 CTAs/SM.
    fused_gate_kernel<<<(N_COLS / (2 * QB)), THREADS>>>(
        (const float4*)x, w, (float2*)out);
}

// round 6
// speedup vs baseline: 1.0063x; 1.0063x over previous
#include <cuda_runtime.h>

#define N_COLS 65536
#define BATCH   256
#define THREADS 256
#define QB      64                     // x-quads per block (= 128 columns)
#define ROW_SPLIT 4                    // row-blocks per column slice
#define ROWS_PB (BATCH / ROW_SPLIT)    // 64 rows per block
#define ROW_STRIDE (N_COLS / 2)        // row stride in float4 (x) / float2 (out) units
#define RGROUPS 4                      // row-groups within block (256 threads / 64 quads)
#define ITERS   (ROWS_PB / RGROUPS)    // 16 rows per thread
#define LBATCH  8                      // loads batched per inner block

// W16_TO_4 exactly as the reference builds it (W[3,1] written twice -> final 1).
__constant__ float c_W[4][16] = {
    { 0, 0, 0, 0,  0, 0, 0, 0,   1,  1,  1,  1,   1,  1,  1,  1},
    { 0, 0, 1, 1,  0, 0, 1, 1,  -1, -1,  0,  0,  -1, -1,  0,  0},
    { 0, 0, 0, 0,  1, 1, 1, 1,  -1, -1, -1, -1,   0,  0,  0,  0},
    { 0, 1,-1, 0, -1, 0,-2,-1,   1,  2,  0,  1,   0,  1, -1,  0}
};

// Fused kernel, balanced grid: block = (128 columns) x (64 rows).
// grid.x = 512 column slices, grid.y = 4 row slices -> 2048 CTAs (3.5 waves
// at 4 CTAs/SM, amortizing wave quantization). Prologue computes softmax +
// projection for the block's 128 columns into smem (recomputed ROW_SPLIT x
// chip-wide; MUFU + w reads hidden under the stream). Main loop: 16 rows per
// thread, unit-stride LDG.128 across the warp, coeffs in registers, 8-deep
// load batches.
__global__ void __launch_bounds__(THREADS, 4)
fused_gate_kernel(const float4* __restrict__ x, const float* __restrict__ w,
                  float2* __restrict__ out) {
    __shared__ float4 s_wc[2 * QB];    // {c0,c1,c2,c3} per column, 2KB

    const int tid = threadIdx.x;
    const int cblk = blockIdx.x;

    // ---- Prologue: per-column softmax -> 4 coefficients (threads 0..127) ----
    if (tid < 2 * QB) {
        const int col = cblk * (2 * QB) + tid;
        float v[16];
        float m = -1e30f;
#pragma unroll
        for (int k = 0; k < 16; k++) {
            v[k] = __ldg(&w[k * N_COLS + col]);
            m = fmaxf(m, v[k]);
        }
        float s = 0.0f;
#pragma unroll
        for (int k = 0; k < 16; k++) {
            v[k] = __expf(v[k] - m);
            s += v[k];
        }
        float inv = 1.0f / s;

        float c0 = 0.f, c1 = 0.f, c2 = 0.f, c3 = 0.f;
#pragma unroll
        for (int k = 0; k < 16; k++) {
            c0 = fmaf(c_W[0][k], v[k], c0);
            c1 = fmaf(c_W[1][k], v[k], c1);
            c2 = fmaf(c_W[2][k], v[k], c2);
            c3 = fmaf(c_W[3][k], v[k], c3);
        }
        s_wc[tid] = make_float4(c0 * inv, c1 * inv, c2 * inv, c3 * inv);
    }
    __syncthreads();

    // ---- Main streaming loop ----
    const int tq = tid & (QB - 1);               // quad within block [0,64)
    const int tr = tid >> 6;                     // row-group [0,4)
    const int gq = cblk * QB + tq;               // global x-quad
    const int b0 = blockIdx.y * ROWS_PB + tr;    // first row for this thread

    const float4 w0 = s_wc[2 * tq];
    const float4 w1 = s_wc[2 * tq + 1];

    const float4* xp = x   + (size_t)b0 * ROW_STRIDE + gq;
    float2*       op = out + (size_t)b0 * ROW_STRIDE + gq;

#pragma unroll
    for (int h = 0; h < ITERS / LBATCH; h++) {
        float4 a[LBATCH];
#pragma unroll
        for (int i = 0; i < LBATCH; i++)
            a[i] = __ldg(xp + (size_t)(RGROUPS * i) * ROW_STRIDE);
#pragma unroll
        for (int i = 0; i < LBATCH; i++) {
            float2 r;
            // out = c0 + c1*A + c2*B + c3*A*B = fma(A, fma(B,c3,c1), fma(B,c2,c0))
            r.x = fmaf(a[i].x, fmaf(a[i].y, w0.w, w0.y), fmaf(a[i].y, w0.z, w0.x));
            r.y = fmaf(a[i].z, fmaf(a[i].w, w1.w, w1.y), fmaf(a[i].w, w1.z, w1.x));
            op[(size_t)(RGROUPS * i) * ROW_STRIDE] = r;
        }
        xp += (size_t)(RGROUPS * LBATCH) * ROW_STRIDE;
        op += (size_t)(RGROUPS * LBATCH) * ROW_STRIDE;
    }
}

extern "C" void kernel_launch(void* const* d_in, const int* in_sizes, int n_in,
                              void* d_out, int out_size) {
    const float* x = (const float*)d_in[0];   // (256, 131072)
    const float* w = (const float*)d_in[1];   // (16, 65536)
    float* out = (float*)d_out;               // (256, 65536)

    dim3 grid(N_COLS / (2 * QB), ROW_SPLIT);  // (512, 4) = 2048 CTAs
    fused_gate_kernel<<<grid, THREADS>>>((const float4*)x, w, (float2*)out);
}